// round 5
// baseline (speedup 1.0000x reference)
#include <cuda_runtime.h>
#include <math.h>
#include <stdint.h>

// Problem constants
#define NN 50000
#define NE 800000
#define NF 128
#define NH 128
#define NH2 64
#define NG 512

// ---------------- scratch (static device globals; no allocation) -------------
__device__ float d_g[(size_t)NN * NF];   // dinv-scaled projected features
__device__ float d_h[(size_t)NN * NF];   // activations
__device__ float d_dinv[NN];
__device__ int   d_cnt[NN];
__device__ int   d_rowptr[NN + 1];
__device__ int   d_cursor[NN];
__device__ int   d_col[NE];
__device__ float d_pool[NG * NH2];
__device__ int   d_gcnt[NG];

// ---------------- init ------------------------------------------------------
__global__ void init_kernel() {
    int i = blockIdx.x * blockDim.x + threadIdx.x;
    if (i < NN) d_cnt[i] = 0;
    if (i < NG * NH2) d_pool[i] = 0.0f;
    if (i < NG) d_gcnt[i] = 0;
}

// ---------------- degree count (1 edge/thread; self-loop implicit +1) --------
__global__ void count_kernel(const int* __restrict__ ei) {
    int e = blockIdx.x * blockDim.x + threadIdx.x;
    if (e < NE) atomicAdd(&d_cnt[ei[NE + e]], 1);
}

// ---------------- single-block chunked scan (one barrier round) --------------
__global__ void scan_kernel() {
    const int C = (NN + 1023) / 1024;   // 49 elements per thread
    int tid = threadIdx.x, lane = tid & 31, wid = tid >> 5;
    int base = tid * C;
    int total = 0;
    #pragma unroll 7
    for (int j = 0; j < C; j++) {
        int i = base + j;
        if (i < NN) total += d_cnt[i];
    }
    __shared__ int wsum[32];
    int x = total;
    #pragma unroll
    for (int o = 1; o < 32; o <<= 1) {
        int t = __shfl_up_sync(0xFFFFFFFFu, x, o);
        if (lane >= o) x += t;
    }
    if (lane == 31) wsum[wid] = x;
    __syncthreads();
    if (wid == 0) {
        int w = wsum[lane];
        #pragma unroll
        for (int o = 1; o < 32; o <<= 1) {
            int t = __shfl_up_sync(0xFFFFFFFFu, w, o);
            if (lane >= o) w += t;
        }
        wsum[lane] = w;
    }
    __syncthreads();
    int run = (wid > 0 ? wsum[wid - 1] : 0) + x - total;  // exclusive prefix
    #pragma unroll 7
    for (int j = 0; j < C; j++) {
        int i = base + j;
        if (i < NN) {
            int v = d_cnt[i];
            d_rowptr[i] = run;
            d_cursor[i] = run;
            d_dinv[i]   = rsqrtf((float)(v + 1));  // deg includes self-loop
            run += v;
        }
    }
    if (tid == 1023) d_rowptr[NN] = run;  // == NE
}

// ---------------- CSR fill (1 edge/thread) -----------------------------------
__global__ void fill_kernel(const int* __restrict__ ei) {
    int e = blockIdx.x * blockDim.x + threadIdx.x;
    if (e < NE) {
        int s = ei[e];
        int d = ei[NE + e];
        int p = atomicAdd(&d_cursor[d], 1);
        d_col[p] = s;
    }
}

// ---------------- GEMM: d_g = dinv[row] * (A @ W) ----------------------------
template <int K, int N, int SRC>   // SRC 0: A = param (x), 1: A = d_h
__global__ void gemm_scale_kernel(const float* __restrict__ Aparam,
                                  const float* __restrict__ W, int M) {
    constexpr int TN = N / 16;
    __shared__ float As[8][128];
    __shared__ float Ws[8][N];
    const float* __restrict__ A = (SRC == 0) ? Aparam : d_h;

    int tid = threadIdx.x;
    int m0 = blockIdx.x * 128;
    int ty = tid >> 4, tx = tid & 15;
    int mb = ty * 8, nb = tx * TN;

    float acc[8][TN];
    #pragma unroll
    for (int i = 0; i < 8; i++)
        #pragma unroll
        for (int j = 0; j < TN; j++) acc[i][j] = 0.0f;

    int arow = tid >> 1;
    int ac = (tid & 1) * 4;
    bool aok = (m0 + arow) < M;
    const float* Ap = A + (size_t)(m0 + arow) * K + ac;

    for (int k0 = 0; k0 < K; k0 += 8) {
        float4 av = aok ? *(const float4*)(Ap + k0) : make_float4(0.f, 0.f, 0.f, 0.f);
        float4 wv = make_float4(0.f, 0.f, 0.f, 0.f);
        int wrow, wc;
        if (N == 128) {
            wrow = tid >> 5; wc = (tid & 31) * 4;
            wv = *(const float4*)&W[(k0 + wrow) * N + wc];
        } else {
            wrow = tid >> 4; wc = (tid & 15) * 4;
            if (tid < 128) wv = *(const float4*)&W[(k0 + wrow) * N + wc];
        }
        __syncthreads();
        As[ac + 0][arow] = av.x;
        As[ac + 1][arow] = av.y;
        As[ac + 2][arow] = av.z;
        As[ac + 3][arow] = av.w;
        if (N == 128 || tid < 128) *(float4*)&Ws[wrow][wc] = wv;
        __syncthreads();
        #pragma unroll
        for (int k = 0; k < 8; k++) {
            float a0[8];
            *(float4*)(a0)     = *(float4*)&As[k][mb];
            *(float4*)(a0 + 4) = *(float4*)&As[k][mb + 4];
            float b0[TN];
            #pragma unroll
            for (int j4 = 0; j4 < TN; j4 += 4)
                *(float4*)(b0 + j4) = *(float4*)&Ws[k][nb + j4];
            #pragma unroll
            for (int i = 0; i < 8; i++)
                #pragma unroll
                for (int j = 0; j < TN; j++)
                    acc[i][j] = fmaf(a0[i], b0[j], acc[i][j]);
        }
    }

    #pragma unroll
    for (int i = 0; i < 8; i++) {
        int row = m0 + mb + i;
        if (row < M) {
            float s = d_dinv[row];
            #pragma unroll
            for (int j4 = 0; j4 < TN; j4 += 4) {
                float4 v;
                v.x = acc[i][j4 + 0] * s;
                v.y = acc[i][j4 + 1] * s;
                v.z = acc[i][j4 + 2] * s;
                v.w = acc[i][j4 + 3] * s;
                *(float4*)&d_g[(size_t)row * N + nb + j4] = v;
            }
        }
    }
}

// ---------------- agg F=128: warp/node, float4 lanes, relu -> d_h -----------
// out[i] = relu( dinv[i] * ( g[i] + sum_c g[c] ) + b ),  g = dinv.(AW)
__global__ void agg128_kernel(const float* __restrict__ bias) {
    int warp = threadIdx.x >> 5, lane = threadIdx.x & 31;
    int i = blockIdx.x * 8 + warp;
    if (i >= NN) return;
    const float4* __restrict__ g4 = (const float4*)d_g;
    float4 acc = g4[(size_t)i * 32 + lane];   // self-loop term
    int s = d_rowptr[i], e = d_rowptr[i + 1];
    int k = s;
    for (; k + 8 <= e; k += 8) {
        #pragma unroll
        for (int j = 0; j < 8; j++) {
            int c = d_col[k + j];
            float4 v = g4[(size_t)c * 32 + lane];
            acc.x += v.x; acc.y += v.y; acc.z += v.z; acc.w += v.w;
        }
    }
    for (; k < e; k++) {
        int c = d_col[k];
        float4 v = g4[(size_t)c * 32 + lane];
        acc.x += v.x; acc.y += v.y; acc.z += v.z; acc.w += v.w;
    }
    float di = d_dinv[i];
    float4 b4 = ((const float4*)bias)[lane];
    float4 r;
    r.x = fmaxf(fmaf(di, acc.x, b4.x), 0.0f);
    r.y = fmaxf(fmaf(di, acc.y, b4.y), 0.0f);
    r.z = fmaxf(fmaf(di, acc.z, b4.z), 0.0f);
    r.w = fmaxf(fmaf(di, acc.w, b4.w), 0.0f);
    ((float4*)d_h)[(size_t)i * 32 + lane] = r;
}

// ---------------- agg F=64: warp/node, float2 lanes --------------------------
// MODE 0: relu -> d_h ; MODE 2: no relu, fused pooling atomics
template <int MODE>
__global__ void agg64_kernel(const float* __restrict__ bias,
                             const int* __restrict__ batch) {
    int warp = threadIdx.x >> 5, lane = threadIdx.x & 31;
    int i = blockIdx.x * 8 + warp;
    if (i >= NN) return;
    const float2* __restrict__ g2 = (const float2*)d_g;
    float2 acc = g2[(size_t)i * 32 + lane];   // self-loop term
    int s = d_rowptr[i], e = d_rowptr[i + 1];
    int k = s;
    for (; k + 8 <= e; k += 8) {
        #pragma unroll
        for (int j = 0; j < 8; j++) {
            int c = d_col[k + j];
            float2 v = g2[(size_t)c * 32 + lane];
            acc.x += v.x; acc.y += v.y;
        }
    }
    for (; k < e; k++) {
        int c = d_col[k];
        float2 v = g2[(size_t)c * 32 + lane];
        acc.x += v.x; acc.y += v.y;
    }
    float di = d_dinv[i];
    float2 b2 = ((const float2*)bias)[lane];
    float rx = fmaf(di, acc.x, b2.x);
    float ry = fmaf(di, acc.y, b2.y);
    if (MODE == 0) {
        float2 r; r.x = fmaxf(rx, 0.0f); r.y = fmaxf(ry, 0.0f);
        ((float2*)d_h)[(size_t)i * 32 + lane] = r;
    } else {
        int b = batch[i];
        atomicAdd(&d_pool[b * NH2 + lane * 2 + 0], rx);
        atomicAdd(&d_pool[b * NH2 + lane * 2 + 1], ry);
        if (lane == 0) atomicAdd(&d_gcnt[b], 1);
    }
}

// ---------------- final: sigmoid(mean) @ Wfc + bfc ---------------------------
__global__ void final_kernel(const float* __restrict__ Wfc,
                             const float* __restrict__ bfc,
                             float* __restrict__ out) {
    int gidx = blockIdx.x * (blockDim.x >> 5) + (threadIdx.x >> 5);
    int lane = threadIdx.x & 31;
    if (gidx >= NG) return;
    float cnt = fmaxf((float)d_gcnt[gidx], 1.0f);
    float s0 = d_pool[gidx * NH2 + lane];
    float s1 = d_pool[gidx * NH2 + 32 + lane];
    float z0 = 1.0f / (1.0f + expf(-s0 / cnt));
    float z1 = 1.0f / (1.0f + expf(-s1 / cnt));
    float p = z0 * Wfc[lane] + z1 * Wfc[lane + 32];
    #pragma unroll
    for (int o = 16; o > 0; o >>= 1) p += __shfl_down_sync(0xFFFFFFFFu, p, o);
    if (lane == 0) out[gidx] = p + bfc[0];
}

// ---------------- launch -----------------------------------------------------
extern "C" void kernel_launch(void* const* d_in, const int* in_sizes, int n_in,
                              void* d_out, int out_size) {
    const float* x     = (const float*)d_in[0];
    const int*   ei    = (const int*)d_in[1];
    const int*   batch = (const int*)d_in[2];
    const float* W1    = (const float*)d_in[3];
    const float* b1    = (const float*)d_in[4];
    const float* W2    = (const float*)d_in[5];
    const float* b2    = (const float*)d_in[6];
    const float* W3    = (const float*)d_in[7];
    const float* b3    = (const float*)d_in[8];
    const float* Wfc   = (const float*)d_in[9];
    const float* bfc   = (const float*)d_in[10];
    float* out = (float*)d_out;

    const int gemm_blocks = (NN + 127) / 128;   // 391
    const int agg_blocks  = (NN + 7) / 8;       // 6250

    init_kernel<<<(NN + 255) / 256, 256>>>();
    count_kernel<<<(NE + 255) / 256, 256>>>(ei);
    scan_kernel<<<1, 1024>>>();
    fill_kernel<<<(NE + 255) / 256, 256>>>(ei);

    // layer 1: 128 -> 128, relu
    gemm_scale_kernel<128, 128, 0><<<gemm_blocks, 256>>>(x, W1, NN);
    agg128_kernel<<<agg_blocks, 256>>>(b1);

    // layer 2: 128 -> 64, relu
    gemm_scale_kernel<128, 64, 1><<<gemm_blocks, 256>>>(nullptr, W2, NN);
    agg64_kernel<0><<<agg_blocks, 256>>>(b2, batch);

    // layer 3: 64 -> 64, no relu, fused pooling
    gemm_scale_kernel<64, 64, 1><<<gemm_blocks, 256>>>(nullptr, W3, NN);
    agg64_kernel<2><<<agg_blocks, 256>>>(b3, batch);

    final_kernel<<<(NG + 7) / 8, 256>>>(Wfc, bfc, out);
}

// round 6
// speedup vs baseline: 1.1081x; 1.1081x over previous
#include <cuda_runtime.h>
#include <cuda_fp16.h>
#include <math.h>
#include <stdint.h>

// Problem constants
#define NN 50000
#define NE 800000
#define NF 128
#define NH 128
#define NH2 64
#define NG 512

// ---------------- scratch (static device globals; no allocation) -------------
__device__ __half d_g[(size_t)NN * NF]; // dinv-scaled projected features (fp16)
__device__ float  d_h[(size_t)NN * NF]; // activations (fp32)
__device__ float  d_dinv[NN];
__device__ int    d_cnt[NN];
__device__ int    d_rowptr[NN + 1];
__device__ int    d_cursor[NN];
__device__ int    d_col[NE];
__device__ float  d_pool[NG * NH2];
__device__ int    d_gcnt[NG];

// ---------------- init ------------------------------------------------------
__global__ void init_kernel() {
    int i = blockIdx.x * blockDim.x + threadIdx.x;
    if (i < NN) d_cnt[i] = 0;
    if (i < NG * NH2) d_pool[i] = 0.0f;
    if (i < NG) d_gcnt[i] = 0;
}

// ---------------- degree count (real edges only; self-loop is +1 implicit) --
__global__ void count_kernel(const int* __restrict__ ei) {
    int e = blockIdx.x * blockDim.x + threadIdx.x;
    if (e < NE) {
        int dst = ei[NE + e];
        atomicAdd(&d_cnt[dst], 1);
    }
}

// ---------------- single-block scan: rowptr/cursor/dinv ----------------------
__global__ void scan_kernel() {
    __shared__ int warp_sums[32];
    __shared__ int s_carry;
    int tid = threadIdx.x, lane = tid & 31, wid = tid >> 5;
    if (tid == 0) s_carry = 0;
    __syncthreads();
    for (int base = 0; base < NN; base += 1024) {
        int i = base + tid;
        int v = (i < NN) ? d_cnt[i] : 0;
        int x = v;
        #pragma unroll
        for (int o = 1; o < 32; o <<= 1) {
            int t = __shfl_up_sync(0xFFFFFFFFu, x, o);
            if (lane >= o) x += t;
        }
        if (lane == 31) warp_sums[wid] = x;
        __syncthreads();
        if (wid == 0) {
            int w = warp_sums[lane];
            #pragma unroll
            for (int o = 1; o < 32; o <<= 1) {
                int t = __shfl_up_sync(0xFFFFFFFFu, w, o);
                if (lane >= o) w += t;
            }
            warp_sums[lane] = w;
        }
        __syncthreads();
        int warp_prefix = (wid > 0) ? warp_sums[wid - 1] : 0;
        int incl = s_carry + warp_prefix + x;
        int excl = incl - v;
        if (i < NN) {
            d_rowptr[i] = excl;
            d_cursor[i] = excl;
            d_dinv[i]   = rsqrtf((float)(v + 1));  // deg includes self-loop, >= 1
        }
        __syncthreads();
        if (tid == 1023) s_carry = incl;
        __syncthreads();
    }
    if (threadIdx.x == 0) d_rowptr[NN] = s_carry;
}

// ---------------- CSR fill ---------------------------------------------------
__global__ void fill_kernel(const int* __restrict__ ei) {
    int e = blockIdx.x * blockDim.x + threadIdx.x;
    if (e < NE) {
        int s = ei[e];
        int d = ei[NE + e];
        int p = atomicAdd(&d_cursor[d], 1);
        d_col[p] = s;
    }
}

// ---------------- GEMM: d_g = half( dinv[row] * (A @ W) ) --------------------
// BM=128, BK=8, 256 threads, per-thread 8 x (N/16)
template <int K, int N, int SRC>   // SRC 0: A = param (x), 1: A = d_h
__global__ void gemm_scale_kernel(const float* __restrict__ Aparam,
                                  const float* __restrict__ W, int M) {
    constexpr int TN = N / 16;
    __shared__ float As[8][128];
    __shared__ float Ws[8][N];
    const float* __restrict__ A = (SRC == 0) ? Aparam : d_h;

    int tid = threadIdx.x;
    int m0 = blockIdx.x * 128;
    int ty = tid >> 4, tx = tid & 15;
    int mb = ty * 8, nb = tx * TN;

    float acc[8][TN];
    #pragma unroll
    for (int i = 0; i < 8; i++)
        #pragma unroll
        for (int j = 0; j < TN; j++) acc[i][j] = 0.0f;

    int arow = tid >> 1;
    int ac = (tid & 1) * 4;
    bool aok = (m0 + arow) < M;
    const float* Ap = A + (size_t)(m0 + arow) * K + ac;

    for (int k0 = 0; k0 < K; k0 += 8) {
        float4 av = aok ? *(const float4*)(Ap + k0) : make_float4(0.f, 0.f, 0.f, 0.f);
        float4 wv = make_float4(0.f, 0.f, 0.f, 0.f);
        int wrow, wc;
        if (N == 128) {
            wrow = tid >> 5; wc = (tid & 31) * 4;
            wv = *(const float4*)&W[(k0 + wrow) * N + wc];
        } else {
            wrow = tid >> 4; wc = (tid & 15) * 4;
            if (tid < 128) wv = *(const float4*)&W[(k0 + wrow) * N + wc];
        }
        __syncthreads();
        As[ac + 0][arow] = av.x;
        As[ac + 1][arow] = av.y;
        As[ac + 2][arow] = av.z;
        As[ac + 3][arow] = av.w;
        if (N == 128 || tid < 128) *(float4*)&Ws[wrow][wc] = wv;
        __syncthreads();
        #pragma unroll
        for (int k = 0; k < 8; k++) {
            float a0[8];
            *(float4*)(a0)     = *(float4*)&As[k][mb];
            *(float4*)(a0 + 4) = *(float4*)&As[k][mb + 4];
            float b0[TN];
            #pragma unroll
            for (int j4 = 0; j4 < TN; j4 += 4)
                *(float4*)(b0 + j4) = *(float4*)&Ws[k][nb + j4];
            #pragma unroll
            for (int i = 0; i < 8; i++)
                #pragma unroll
                for (int j = 0; j < TN; j++)
                    acc[i][j] = fmaf(a0[i], b0[j], acc[i][j]);
        }
    }

    #pragma unroll
    for (int i = 0; i < 8; i++) {
        int row = m0 + mb + i;
        if (row < M) {
            float s = d_dinv[row];
            #pragma unroll
            for (int j4 = 0; j4 < TN; j4 += 4) {
                __half2 h0 = __floats2half2_rn(acc[i][j4 + 0] * s, acc[i][j4 + 1] * s);
                __half2 h1 = __floats2half2_rn(acc[i][j4 + 2] * s, acc[i][j4 + 3] * s);
                __half2* p = (__half2*)&d_g[(size_t)row * N + nb + j4];
                p[0] = h0;
                p[1] = h1;
            }
        }
    }
}

// ---------------- aggregation: out[i] = act(dinv[i]*(self + sum g[src]) + b) -
// block per node, F threads; g is fp16, accumulate fp32.
// MODE 0: relu -> d_h ;  MODE 2: no relu, fused pooling atomics
template <int F, int MODE>
__global__ void agg_kernel(const float* __restrict__ bias,
                           const int* __restrict__ batch) {
    int i = blockIdx.x;
    int f = threadIdx.x;
    float acc = __half2float(d_g[(size_t)i * F + f]);   // self-loop term
    int s = d_rowptr[i], e = d_rowptr[i + 1];
    int k = s;
    for (; k + 4 <= e; k += 4) {
        int c0 = d_col[k + 0];
        int c1 = d_col[k + 1];
        int c2 = d_col[k + 2];
        int c3 = d_col[k + 3];
        acc += __half2float(d_g[(size_t)c0 * F + f]);
        acc += __half2float(d_g[(size_t)c1 * F + f]);
        acc += __half2float(d_g[(size_t)c2 * F + f]);
        acc += __half2float(d_g[(size_t)c3 * F + f]);
    }
    for (; k < e; k++) acc += __half2float(d_g[(size_t)d_col[k] * F + f]);
    float v = d_dinv[i] * acc + bias[f];
    if (MODE == 0) {
        d_h[(size_t)i * F + f] = fmaxf(v, 0.0f);
    } else {
        int b = batch[i];
        atomicAdd(&d_pool[b * NH2 + f], v);
        if (f == 0) atomicAdd(&d_gcnt[b], 1);
    }
}

// ---------------- final: sigmoid(mean) @ Wfc + bfc ---------------------------
__global__ void final_kernel(const float* __restrict__ Wfc,
                             const float* __restrict__ bfc,
                             float* __restrict__ out) {
    int gidx = blockIdx.x * (blockDim.x >> 5) + (threadIdx.x >> 5);
    int lane = threadIdx.x & 31;
    if (gidx >= NG) return;
    float cnt = fmaxf((float)d_gcnt[gidx], 1.0f);
    float s0 = d_pool[gidx * NH2 + lane];
    float s1 = d_pool[gidx * NH2 + 32 + lane];
    float z0 = 1.0f / (1.0f + expf(-s0 / cnt));
    float z1 = 1.0f / (1.0f + expf(-s1 / cnt));
    float p = z0 * Wfc[lane] + z1 * Wfc[lane + 32];
    #pragma unroll
    for (int o = 16; o > 0; o >>= 1) p += __shfl_down_sync(0xFFFFFFFFu, p, o);
    if (lane == 0) out[gidx] = p + bfc[0];
}

// ---------------- launch -----------------------------------------------------
extern "C" void kernel_launch(void* const* d_in, const int* in_sizes, int n_in,
                              void* d_out, int out_size) {
    const float* x     = (const float*)d_in[0];
    const int*   ei    = (const int*)d_in[1];
    const int*   batch = (const int*)d_in[2];
    const float* W1    = (const float*)d_in[3];
    const float* b1    = (const float*)d_in[4];
    const float* W2    = (const float*)d_in[5];
    const float* b2    = (const float*)d_in[6];
    const float* W3    = (const float*)d_in[7];
    const float* b3    = (const float*)d_in[8];
    const float* Wfc   = (const float*)d_in[9];
    const float* bfc   = (const float*)d_in[10];
    float* out = (float*)d_out;

    const int gemm_blocks = (NN + 127) / 128;  // 391

    init_kernel<<<(NN + 255) / 256, 256>>>();
    count_kernel<<<(NE + 255) / 256, 256>>>(ei);
    scan_kernel<<<1, 1024>>>();
    fill_kernel<<<(NE + 255) / 256, 256>>>(ei);

    // layer 1: 128 -> 128, relu
    gemm_scale_kernel<128, 128, 0><<<gemm_blocks, 256>>>(x, W1, NN);
    agg_kernel<128, 0><<<NN, 128>>>(b1, batch);

    // layer 2: 128 -> 64, relu
    gemm_scale_kernel<128, 64, 1><<<gemm_blocks, 256>>>(nullptr, W2, NN);
    agg_kernel<64, 0><<<NN, 64>>>(b2, batch);

    // layer 3: 64 -> 64, no relu, fused pooling
    gemm_scale_kernel<64, 64, 1><<<gemm_blocks, 256>>>(nullptr, W3, NN);
    agg_kernel<64, 2><<<NN, 64>>>(b3, batch);

    final_kernel<<<(NG + 7) / 8, 256>>>(Wfc, bfc, out);
}